// round 15
// baseline (speedup 1.0000x reference)
#include <cuda_runtime.h>
#include <cooperative_groups.h>

namespace cg = cooperative_groups;

// Problem constants
#define BB    128
#define TT    32
#define DD    128
#define NSLOT 128
#define BITS  32
#define HH    4
#define UU    256
#define HDW   128
#define CTLW  256
#define OUTW  384
#define MPITCH 36
#define THREADS 640
#define CLN   4        // cluster size = batches per cluster
#define CQ    64       // hctl quarter (Wc col quarter == Wf row quarter)

struct SmemLayout {
    float M[NSLOT * MPITCH];     // 4608
    float ctlX[CLN][CTLW];       // ctl of all 4 batches (slot bi owned by rank bi, pulled)
    float hctl_q[CLN][CQ];       // MY quarter of hctl, all 4 batches
    float opart[CLN][OUTW];      // my k-partial of full o, all 4 batches
    float o_full[OUTW];          // full o of MY batch
    float rW[HH * NSLOT];
    float wW[HH * NSLOT];
    float hisW[HH * NSLOT];
    float rv[HDW];
    float minv[NSLOT];
    float beta_s[HH * NSLOT];
    float g_s[HH * NSLOT];
    float Wg_s[HH * NSLOT];
    float er_s[HH * BITS];
    float ad_s[HH * BITS];
    float bc_s[CQ];              // my col-quarter of bc
    float bf_s[OUTW];            // FULL bf (bias added after reduction)
    float wpinC[256 * CQ];       // 16384  ALL Wc rows, my col-quarter
    float wpinF[CQ * OUTW];      // 24576  Wf ROW-quarter [r*64, r*64+64), all 384 cols
};
// 52,800 floats = 211,200 bytes <= 232,448 B opt-in

// ---- fused cosine-addressing: in-register key norm + logits + softmax + blend ----
__device__ __forceinline__ void fused_address(SmemLayout* s, const float* __restrict__ keys,
                                              float* __restrict__ dst, int h, int lane)
{
    const float4* K = reinterpret_cast<const float4*>(keys);
    float4 k0 = K[0], k1 = K[1], k2 = K[2], k3 = K[3];
    float4 k4 = K[4], k5 = K[5], k6 = K[6], k7 = K[7];
    float ss = k0.x*k0.x + k0.y*k0.y + k0.z*k0.z + k0.w*k0.w
             + k1.x*k1.x + k1.y*k1.y + k1.z*k1.z + k1.w*k1.w
             + k2.x*k2.x + k2.y*k2.y + k2.z*k2.z + k2.w*k2.w
             + k3.x*k3.x + k3.y*k3.y + k3.z*k3.z + k3.w*k3.w
             + k4.x*k4.x + k4.y*k4.y + k4.z*k4.z + k4.w*k4.w
             + k5.x*k5.x + k5.y*k5.y + k5.z*k5.z + k5.w*k5.w
             + k6.x*k6.x + k6.y*k6.y + k6.z*k6.z + k6.w*k6.w
             + k7.x*k7.x + k7.y*k7.y + k7.z*k7.z + k7.w*k7.w;
    float kinv_h = rsqrtf(fmaxf(ss, 1e-12f));
    float e[4];
#pragma unroll
    for (int i = 0; i < 4; ++i) {
        int n = lane + i * 32;
        const float4* Mr = reinterpret_cast<const float4*>(&s->M[n * MPITCH]);
        float4 m0 = Mr[0], m1 = Mr[1], m2 = Mr[2], m3 = Mr[3];
        float4 m4 = Mr[4], m5 = Mr[5], m6 = Mr[6], m7 = Mr[7];
        float raw = m0.x*k0.x + m0.y*k0.y + m0.z*k0.z + m0.w*k0.w
                  + m1.x*k1.x + m1.y*k1.y + m1.z*k1.z + m1.w*k1.w
                  + m2.x*k2.x + m2.y*k2.y + m2.z*k2.z + m2.w*k2.w
                  + m3.x*k3.x + m3.y*k3.y + m3.z*k3.z + m3.w*k3.w
                  + m4.x*k4.x + m4.y*k4.y + m4.z*k4.z + m4.w*k4.w
                  + m5.x*k5.x + m5.y*k5.y + m5.z*k5.z + m5.w*k5.w
                  + m6.x*k6.x + m6.y*k6.y + m6.z*k6.z + m6.w*k6.w
                  + m7.x*k7.x + m7.y*k7.y + m7.z*k7.z + m7.w*k7.w;
        e[i] = -s->beta_s[h * NSLOT + n] * kinv_h * s->minv[n] * raw;
    }
    float m = fmaxf(fmaxf(e[0], e[1]), fmaxf(e[2], e[3]));
#pragma unroll
    for (int off = 16; off > 0; off >>= 1) m = fmaxf(m, __shfl_xor_sync(0xffffffffu, m, off));
    float sum = 0.f;
#pragma unroll
    for (int i = 0; i < 4; ++i) { e[i] = __expf(e[i] - m); sum += e[i]; }
#pragma unroll
    for (int off = 16; off > 0; off >>= 1) sum += __shfl_xor_sync(0xffffffffu, sum, off);
    float inv = 1.0f / sum;
#pragma unroll
    for (int i = 0; i < 4; ++i) {
        int n = lane + i * 32;
        float gg = s->g_s[h * NSLOT + n];
        dst[h * NSLOT + n] = gg * (e[i] * inv) + (1.f - gg) * dst[h * NSLOT + n];
    }
}

__global__ __cluster_dims__(CLN, 1, 1) __launch_bounds__(THREADS, 1)
void uic_kernel(const float* __restrict__ x, const float* __restrict__ beta,
                const float* __restrict__ g, const float* __restrict__ erase,
                const float* __restrict__ add, const float* __restrict__ Wg,
                const float* __restrict__ M0, const float* __restrict__ read0,
                const float* __restrict__ readW0, const float* __restrict__ writeW0,
                const float* __restrict__ Wc, const float* __restrict__ bc,
                const float* __restrict__ Wf, const float* __restrict__ bf,
                float* __restrict__ out)
{
    extern __shared__ float smem_raw[];
    SmemLayout* s = reinterpret_cast<SmemLayout*>(smem_raw);
    cg::cluster_group cl = cg::this_cluster();
    const int r   = (int)cl.block_rank();
    const int b   = blockIdx.x;
    const int tid = threadIdx.x;
    const int lane = tid & 31;
    const int warp = tid >> 5;

    // ---------------- init ----------------
    for (int idx = tid; idx < NSLOT * BITS; idx += THREADS) {
        int n = idx >> 5, d = idx & 31;
        s->M[n * MPITCH + d] = M0[b * NSLOT * BITS + idx];
    }
    for (int idx = tid; idx < HH * NSLOT; idx += THREADS) {
        s->rW[idx]     = readW0[b * HH * NSLOT + idx];
        s->wW[idx]     = writeW0[b * HH * NSLOT + idx];
        s->hisW[idx]   = 0.f;
        s->beta_s[idx] = beta[idx];
        s->g_s[idx]    = g[idx];
        s->Wg_s[idx]   = Wg[b * HH * NSLOT + idx];
    }
    for (int idx = tid; idx < HDW; idx += THREADS) {
        s->rv[idx]   = read0[b * HDW + idx];
        s->er_s[idx] = erase[b * HDW + idx];
        s->ad_s[idx] = add[b * HDW + idx];
    }
    for (int idx = tid; idx < CQ; idx += THREADS)   s->bc_s[idx] = bc[r * CQ + idx];
    for (int idx = tid; idx < OUTW; idx += THREADS) s->bf_s[idx] = bf[idx];
    // Wc col-quarter
    for (int idx = tid; idx < 256 * CQ; idx += THREADS) {
        int n = idx >> 6, c = idx & (CQ - 1);
        s->wpinC[idx] = Wc[n * UU + r * CQ + c];
    }
    // Wf ROW-quarter: rows [r*64, r*64+64), all 384 cols
    for (int idx = tid; idx < CQ * OUTW; idx += THREADS) {
        int n = idx / OUTW, c = idx - n * OUTW;
        s->wpinF[idx] = Wf[(r * CQ + n) * OUTW + c];
    }
    // prologue: minv for t=0
    __syncthreads();
    if (tid < NSLOT) {
        const float4* Mr = reinterpret_cast<const float4*>(&s->M[tid * MPITCH]);
        float ss = 0.f;
#pragma unroll
        for (int i = 0; i < 8; ++i) {
            float4 v = Mr[i];
            ss += v.x * v.x + v.y * v.y + v.z * v.z + v.w * v.w;
        }
        s->minv[tid] = rsqrtf(fmaxf(ss, 1e-12f));
    }
    cl.sync();   // smem (incl. pinned weights) visible cluster-wide
    __syncthreads();

    for (int t = 0; t < TT; ++t) {
        // ---- ALPHA: read addressing (w0-3) | P9 of t-1 (w4-7) | x(t) load (w16-19) ----
        if (warp < HH) {
            fused_address(s, &s->rv[warp * BITS], s->rW, warp, lane);
        } else if (warp < 2 * HH) {
            if (t > 0) {
                int h = warp - HH;
                float v[4];
#pragma unroll
                for (int i = 0; i < 4; ++i) {
                    int n = lane + i * 32;
                    v[i] = s->Wg_s[h * NSLOT + n] * s->hisW[h * NSLOT + n];
                }
                float m = fmaxf(fmaxf(v[0], v[1]), fmaxf(v[2], v[3]));
#pragma unroll
                for (int off = 16; off > 0; off >>= 1) m = fmaxf(m, __shfl_xor_sync(0xffffffffu, m, off));
                float sum = 0.f;
#pragma unroll
                for (int i = 0; i < 4; ++i) { v[i] = __expf(v[i] - m); sum += v[i]; }
#pragma unroll
                for (int off = 16; off > 0; off >>= 1) sum += __shfl_xor_sync(0xffffffffu, sum, off);
                float inv = 1.0f / sum;
#pragma unroll
                for (int i = 0; i < 4; ++i) {
                    int n = lane + i * 32;
                    float wnew = s->wW[h * NSLOT + n] * (v[i] * inv);
                    s->wW[h * NSLOT + n] = wnew;
                    s->hisW[h * NSLOT + n] += wnew;
                }
            }
        } else if (tid >= 512) {
            s->ctlX[r][tid - 512] = x[b * TT * DD + t * DD + (tid - 512)];
        }
        __syncthreads();

        // ---- P3: read_input = rW @ M, single phase with warp butterfly reduce ----
        if (tid < 512) {
            int half = lane >> 4;            // 0/1
            int sub  = lane & 15;
            int task = warp * 2 + half;      // 0..31 = h*8 + d4
            int h = task >> 3, d4 = task & 7;
            const float4* M4 = reinterpret_cast<const float4*>(s->M);
            const float* rwh = &s->rW[h * NSLOT];
            float4 a = make_float4(0.f, 0.f, 0.f, 0.f);
#pragma unroll
            for (int i = 0; i < 8; ++i) {
                int n = sub + i * 16;        // stride-16 rows: conflict-free phases
                float4 mm = M4[n * 9 + d4];
                float w = rwh[n];
                a.x += w * mm.x; a.y += w * mm.y; a.z += w * mm.z; a.w += w * mm.w;
            }
#pragma unroll
            for (int off = 8; off > 0; off >>= 1) {
                a.x += __shfl_xor_sync(0xffffffffu, a.x, off);
                a.y += __shfl_xor_sync(0xffffffffu, a.y, off);
                a.z += __shfl_xor_sync(0xffffffffu, a.z, off);
                a.w += __shfl_xor_sync(0xffffffffu, a.w, off);
            }
            if (sub == 0)
                reinterpret_cast<float4*>(&s->ctlX[r][DD])[task] = a;
        }
        // ---- S1: ctl ready; gather peers' ctl ----
        cl.sync();
        if (tid < 192) {
            int p = tid / 64, q = tid & 63;
            int pr = p + (p >= r);
            const float4* src = (const float4*)cl.map_shared_rank((void*)s->ctlX[pr], pr);
            reinterpret_cast<float4*>(s->ctlX[pr])[q] = src[q];
        }
        __syncthreads();

        // ---- P4: hctl quarter for ALL 4 batches, warp-shuffle split-k ----
        // warp w (0..15) owns col4=w; lane = bi*8 + sub; sub covers rows [sub*32, +32)
        if (tid < 512) {
            int col4 = warp;
            int bi  = lane >> 3;
            int sub = lane & 7;
            const float4* wp = reinterpret_cast<const float4*>(s->wpinC);
            const float* cb = s->ctlX[bi];
            float4 a = make_float4(0.f, 0.f, 0.f, 0.f);
            int n0 = sub * 32;
#pragma unroll 8
            for (int n = n0; n < n0 + 32; ++n) {
                float4 w = wp[n * 16 + col4];
                float v = cb[n];
                a.x += v * w.x; a.y += v * w.y; a.z += v * w.z; a.w += v * w.w;
            }
#pragma unroll
            for (int off = 4; off > 0; off >>= 1) {
                a.x += __shfl_xor_sync(0xffffffffu, a.x, off);
                a.y += __shfl_xor_sync(0xffffffffu, a.y, off);
                a.z += __shfl_xor_sync(0xffffffffu, a.z, off);
                a.w += __shfl_xor_sync(0xffffffffu, a.w, off);
            }
            if (sub == 0) {
                int c = col4 * 4;
                s->hctl_q[bi][c]     = fmaxf(a.x + s->bc_s[c],     0.f);
                s->hctl_q[bi][c + 1] = fmaxf(a.y + s->bc_s[c + 1], 0.f);
                s->hctl_q[bi][c + 2] = fmaxf(a.z + s->bc_s[c + 2], 0.f);
                s->hctl_q[bi][c + 3] = fmaxf(a.w + s->bc_s[c + 3], 0.f);
            }
        }
        __syncthreads();

        // ---- P5: o k-partial (full 384 cols) for ALL 4 batches; Wf row-quarter ----
        // 384 threads: warps 0-2 bi=0, 3-5 bi=1, ...; col4 = tid % 96
        if (tid < 384) {
            int bi   = tid / 96;
            int col4 = tid - bi * 96;
            const float4* wp = reinterpret_cast<const float4*>(s->wpinF);
            const float* hb = s->hctl_q[bi];
            float4 a = make_float4(0.f, 0.f, 0.f, 0.f);
#pragma unroll 8
            for (int n = 0; n < CQ; ++n) {
                float4 w = wp[n * 96 + col4];
                float v = hb[n];
                a.x += v * w.x; a.y += v * w.y; a.z += v * w.z; a.w += v * w.w;
            }
            reinterpret_cast<float4*>(s->opart[bi])[col4] = a;
        }
        // ---- S2: o-partials ready; owner CTA reduces its batch's 4 partials ----
        cl.sync();
        if (tid < 96) {
            int q = tid;
            float4 acc = reinterpret_cast<const float4*>(s->opart[r])[q];
#pragma unroll
            for (int p = 0; p < 3; ++p) {
                int pr = p + (p >= r);
                const float4* src = (const float4*)cl.map_shared_rank((void*)s->opart[r], pr);
                float4 v = src[q];
                acc.x += v.x; acc.y += v.y; acc.z += v.z; acc.w += v.w;
            }
            float4 bv = reinterpret_cast<const float4*>(s->bf_s)[q];
            acc.x += bv.x; acc.y += bv.y; acc.z += bv.z; acc.w += bv.w;
            reinterpret_cast<float4*>(s->o_full)[q] = acc;
        }
        __syncthreads();

        // ---- BETA: write addressing (w0-3, in-reg kinvw) | out emit | rv stash ----
        if (warp < HH) {
            fused_address(s, &s->o_full[CTLW + warp * BITS], s->wW, warp, lane);
        } else if (tid < 256) {
            out[b * TT * DD + t * DD + (tid - 128)] = s->o_full[tid - 128];
        } else if (tid < 384) {
            s->rv[tid - 256] = s->o_full[tid - 128];
        }
        __syncthreads();

        // ---- P8: M update + fused M-norms (pre-Pt wW) ----
        if (tid < 512) {
            int n  = tid >> 2;
            int d8 = (tid & 3) * 8;
            float w0 = s->wW[n], w1 = s->wW[NSLOT + n];
            float w2 = s->wW[2 * NSLOT + n], w3 = s->wW[3 * NSLOT + n];
            float ss = 0.f;
            float4* Mp = reinterpret_cast<float4*>(&s->M[n * MPITCH + d8]);
#pragma unroll
            for (int q = 0; q < 2; ++q) {
                int db = d8 + q * 4;
                float4 mv = Mp[q];
                float4 e0 = *reinterpret_cast<const float4*>(&s->er_s[0 * BITS + db]);
                float4 e1 = *reinterpret_cast<const float4*>(&s->er_s[1 * BITS + db]);
                float4 e2 = *reinterpret_cast<const float4*>(&s->er_s[2 * BITS + db]);
                float4 e3 = *reinterpret_cast<const float4*>(&s->er_s[3 * BITS + db]);
                float4 a0 = *reinterpret_cast<const float4*>(&s->ad_s[0 * BITS + db]);
                float4 a1 = *reinterpret_cast<const float4*>(&s->ad_s[1 * BITS + db]);
                float4 a2 = *reinterpret_cast<const float4*>(&s->ad_s[2 * BITS + db]);
                float4 a3 = *reinterpret_cast<const float4*>(&s->ad_s[3 * BITS + db]);
                float4 nm;
                float ew, aw;
                ew = w0*e0.x + w1*e1.x + w2*e2.x + w3*e3.x;
                aw = w0*a0.x + w1*a1.x + w2*a2.x + w3*a3.x;
                nm.x = mv.x * (1.f - ew) + aw;
                ew = w0*e0.y + w1*e1.y + w2*e2.y + w3*e3.y;
                aw = w0*a0.y + w1*a1.y + w2*a2.y + w3*a3.y;
                nm.y = mv.y * (1.f - ew) + aw;
                ew = w0*e0.z + w1*e1.z + w2*e2.z + w3*e3.z;
                aw = w0*a0.z + w1*a1.z + w2*a2.z + w3*a3.z;
                nm.z = mv.z * (1.f - ew) + aw;
                ew = w0*e0.w + w1*e1.w + w2*e2.w + w3*e3.w;
                aw = w0*a0.w + w1*a1.w + w2*a2.w + w3*a3.w;
                nm.w = mv.w * (1.f - ew) + aw;
                Mp[q] = nm;
                ss += nm.x*nm.x + nm.y*nm.y + nm.z*nm.z + nm.w*nm.w;
            }
            ss += __shfl_xor_sync(0xffffffffu, ss, 1);
            ss += __shfl_xor_sync(0xffffffffu, ss, 2);
            if ((tid & 3) == 0) s->minv[n] = rsqrtf(fmaxf(ss, 1e-12f));
        }
        __syncthreads();
    }
    cl.sync();   // no CTA exits while peers' DSMEM pulls could be in flight
}

extern "C" void kernel_launch(void* const* d_in, const int* in_sizes, int n_in,
                              void* d_out, int out_size)
{
    const float* x       = (const float*)d_in[0];
    const float* beta    = (const float*)d_in[1];
    const float* g       = (const float*)d_in[2];
    const float* erase   = (const float*)d_in[3];
    const float* add     = (const float*)d_in[4];
    const float* Wg      = (const float*)d_in[5];
    const float* M0      = (const float*)d_in[6];
    const float* read0   = (const float*)d_in[7];
    const float* readW0  = (const float*)d_in[8];
    const float* writeW0 = (const float*)d_in[9];
    // d_in[10] = S0   (dead)
    const float* Wc      = (const float*)d_in[11];
    const float* bc      = (const float*)d_in[12];
    const float* Wf      = (const float*)d_in[13];
    const float* bf      = (const float*)d_in[14];
    // d_in[15..17] = Wi, Ui, b_gru (dead)

    (void)in_sizes; (void)n_in; (void)out_size;

    cudaFuncSetAttribute(uic_kernel, cudaFuncAttributeMaxDynamicSharedMemorySize,
                         (int)sizeof(SmemLayout));
    uic_kernel<<<BB, THREADS, sizeof(SmemLayout)>>>(x, beta, g, erase, add, Wg,
                                                    M0, read0, readW0, writeW0,
                                                    Wc, bc, Wf, bf, (float*)d_out);
}

// round 17
// speedup vs baseline: 2.6990x; 2.6990x over previous
#include <cuda_runtime.h>
#include <cooperative_groups.h>

namespace cg = cooperative_groups;

// Problem constants
#define BB    128
#define TT    32
#define DD    128
#define NSLOT 128
#define BITS  32
#define HH    4
#define UU    256
#define HDW   128
#define CTLW  256
#define OUTW  384
#define MPITCH 36
#define THREADS 512
#define CLN   4        // cluster size = batches per cluster
#define CQ    64       // hctl quarter (Wc col quarter == Wf row quarter)

struct SmemLayout {
    float M[NSLOT * MPITCH];     // 4608
    float ctlX[CLN][CTLW];       // ctl of all 4 batches (slot bi owned by rank bi, pulled)
    float hctl_q[CLN][CQ];       // MY hctl quarter, all 4 batches (local only)
    float opart[CLN][OUTW];      // my k-partial of full o, all 4 batches
    float o_full[OUTW];          // full o of MY batch
    float rW[HH * NSLOT];
    float wW[HH * NSLOT];
    float hisW[HH * NSLOT];
    float rv[HDW];
    float minv[NSLOT];
    float beta_s[HH * NSLOT];
    float g_s[HH * NSLOT];
    float Wg_s[HH * NSLOT];
    float er_s[HH * BITS];
    float ad_s[HH * BITS];
    float bc_s[CQ];              // my col-quarter of bc
    float bf_s[OUTW];            // FULL bf (added after cross-CTA reduction)
    float red[4368];             // P4 split-k scratch (padded slots)
    float wpinC[256 * CQ];       // 16384  ALL Wc rows, my col-quarter
    float wpinF[CQ * OUTW];      // 24576  Wf ROW-quarter [r*64,+64), all 384 cols
};
// 57,168 floats = 228,672 bytes <= 232,448 B opt-in

// ---- fused cosine-addressing: in-register key norm + logits + softmax + blend ----
__device__ __forceinline__ void fused_address(SmemLayout* s, const float* __restrict__ keys,
                                              float* __restrict__ dst, int h, int lane)
{
    const float4* K = reinterpret_cast<const float4*>(keys);
    float4 k0 = K[0], k1 = K[1], k2 = K[2], k3 = K[3];
    float4 k4 = K[4], k5 = K[5], k6 = K[6], k7 = K[7];
    float ss = k0.x*k0.x + k0.y*k0.y + k0.z*k0.z + k0.w*k0.w
             + k1.x*k1.x + k1.y*k1.y + k1.z*k1.z + k1.w*k1.w
             + k2.x*k2.x + k2.y*k2.y + k2.z*k2.z + k2.w*k2.w
             + k3.x*k3.x + k3.y*k3.y + k3.z*k3.z + k3.w*k3.w
             + k4.x*k4.x + k4.y*k4.y + k4.z*k4.z + k4.w*k4.w
             + k5.x*k5.x + k5.y*k5.y + k5.z*k5.z + k5.w*k5.w
             + k6.x*k6.x + k6.y*k6.y + k6.z*k6.z + k6.w*k6.w
             + k7.x*k7.x + k7.y*k7.y + k7.z*k7.z + k7.w*k7.w;
    float kinv_h = rsqrtf(fmaxf(ss, 1e-12f));
    float e[4];
#pragma unroll
    for (int i = 0; i < 4; ++i) {
        int n = lane + i * 32;
        const float4* Mr = reinterpret_cast<const float4*>(&s->M[n * MPITCH]);
        float4 m0 = Mr[0], m1 = Mr[1], m2 = Mr[2], m3 = Mr[3];
        float4 m4 = Mr[4], m5 = Mr[5], m6 = Mr[6], m7 = Mr[7];
        float raw = m0.x*k0.x + m0.y*k0.y + m0.z*k0.z + m0.w*k0.w
                  + m1.x*k1.x + m1.y*k1.y + m1.z*k1.z + m1.w*k1.w
                  + m2.x*k2.x + m2.y*k2.y + m2.z*k2.z + m2.w*k2.w
                  + m3.x*k3.x + m3.y*k3.y + m3.z*k3.z + m3.w*k3.w
                  + m4.x*k4.x + m4.y*k4.y + m4.z*k4.z + m4.w*k4.w
                  + m5.x*k5.x + m5.y*k5.y + m5.z*k5.z + m5.w*k5.w
                  + m6.x*k6.x + m6.y*k6.y + m6.z*k6.z + m6.w*k6.w
                  + m7.x*k7.x + m7.y*k7.y + m7.z*k7.z + m7.w*k7.w;
        e[i] = -s->beta_s[h * NSLOT + n] * kinv_h * s->minv[n] * raw;
    }
    float m = fmaxf(fmaxf(e[0], e[1]), fmaxf(e[2], e[3]));
#pragma unroll
    for (int off = 16; off > 0; off >>= 1) m = fmaxf(m, __shfl_xor_sync(0xffffffffu, m, off));
    float sum = 0.f;
#pragma unroll
    for (int i = 0; i < 4; ++i) { e[i] = __expf(e[i] - m); sum += e[i]; }
#pragma unroll
    for (int off = 16; off > 0; off >>= 1) sum += __shfl_xor_sync(0xffffffffu, sum, off);
    float inv = 1.0f / sum;
#pragma unroll
    for (int i = 0; i < 4; ++i) {
        int n = lane + i * 32;
        float gg = s->g_s[h * NSLOT + n];
        dst[h * NSLOT + n] = gg * (e[i] * inv) + (1.f - gg) * dst[h * NSLOT + n];
    }
}

__global__ __cluster_dims__(CLN, 1, 1) __launch_bounds__(THREADS, 1)
void uic_kernel(const float* __restrict__ x, const float* __restrict__ beta,
                const float* __restrict__ g, const float* __restrict__ erase,
                const float* __restrict__ add, const float* __restrict__ Wg,
                const float* __restrict__ M0, const float* __restrict__ read0,
                const float* __restrict__ readW0, const float* __restrict__ writeW0,
                const float* __restrict__ Wc, const float* __restrict__ bc,
                const float* __restrict__ Wf, const float* __restrict__ bf,
                float* __restrict__ out)
{
    extern __shared__ float smem_raw[];
    SmemLayout* s = reinterpret_cast<SmemLayout*>(smem_raw);
    cg::cluster_group cl = cg::this_cluster();
    const int r   = (int)cl.block_rank();
    const int b   = blockIdx.x;
    const int tid = threadIdx.x;
    const int lane = tid & 31;
    const int warp = tid >> 5;

    // ---------------- init ----------------
    for (int idx = tid; idx < NSLOT * BITS; idx += THREADS) {
        int n = idx >> 5, d = idx & 31;
        s->M[n * MPITCH + d] = M0[b * NSLOT * BITS + idx];
    }
    for (int idx = tid; idx < HH * NSLOT; idx += THREADS) {
        s->rW[idx]     = readW0[b * HH * NSLOT + idx];
        s->wW[idx]     = writeW0[b * HH * NSLOT + idx];
        s->hisW[idx]   = 0.f;
        s->beta_s[idx] = beta[idx];
        s->g_s[idx]    = g[idx];
        s->Wg_s[idx]   = Wg[b * HH * NSLOT + idx];
    }
    for (int idx = tid; idx < HDW; idx += THREADS) {
        s->rv[idx]   = read0[b * HDW + idx];
        s->er_s[idx] = erase[b * HDW + idx];
        s->ad_s[idx] = add[b * HDW + idx];
    }
    for (int idx = tid; idx < CQ; idx += THREADS)   s->bc_s[idx] = bc[r * CQ + idx];
    for (int idx = tid; idx < OUTW; idx += THREADS) s->bf_s[idx] = bf[idx];
    // Wc col-quarter
    for (int idx = tid; idx < 256 * CQ; idx += THREADS) {
        int n = idx >> 6, c = idx & (CQ - 1);
        s->wpinC[idx] = Wc[n * UU + r * CQ + c];
    }
    // Wf ROW-quarter: rows [r*64, r*64+64), all 384 cols
    for (int idx = tid; idx < CQ * OUTW; idx += THREADS) {
        int n = idx / OUTW, c = idx - n * OUTW;
        s->wpinF[idx] = Wf[(r * CQ + n) * OUTW + c];
    }
    // prologue: minv for t=0
    __syncthreads();
    if (tid < NSLOT) {
        const float4* Mr = reinterpret_cast<const float4*>(&s->M[tid * MPITCH]);
        float ss = 0.f;
#pragma unroll
        for (int i = 0; i < 8; ++i) {
            float4 v = Mr[i];
            ss += v.x * v.x + v.y * v.y + v.z * v.z + v.w * v.w;
        }
        s->minv[tid] = rsqrtf(fmaxf(ss, 1e-12f));
    }
    cl.sync();   // smem (incl. pinned weights) visible cluster-wide
    __syncthreads();

    for (int t = 0; t < TT; ++t) {
        // ---- ALPHA: read addressing (w0-3) | P9 of t-1 (w4-7) | x(t) load (w8-11) ----
        if (warp < HH) {
            fused_address(s, &s->rv[warp * BITS], s->rW, warp, lane);
        } else if (warp < 2 * HH) {
            if (t > 0) {
                int h = warp - HH;
                float v[4];
#pragma unroll
                for (int i = 0; i < 4; ++i) {
                    int n = lane + i * 32;
                    v[i] = s->Wg_s[h * NSLOT + n] * s->hisW[h * NSLOT + n];
                }
                float m = fmaxf(fmaxf(v[0], v[1]), fmaxf(v[2], v[3]));
#pragma unroll
                for (int off = 16; off > 0; off >>= 1) m = fmaxf(m, __shfl_xor_sync(0xffffffffu, m, off));
                float sum = 0.f;
#pragma unroll
                for (int i = 0; i < 4; ++i) { v[i] = __expf(v[i] - m); sum += v[i]; }
#pragma unroll
                for (int off = 16; off > 0; off >>= 1) sum += __shfl_xor_sync(0xffffffffu, sum, off);
                float inv = 1.0f / sum;
#pragma unroll
                for (int i = 0; i < 4; ++i) {
                    int n = lane + i * 32;
                    float wnew = s->wW[h * NSLOT + n] * (v[i] * inv);
                    s->wW[h * NSLOT + n] = wnew;
                    s->hisW[h * NSLOT + n] += wnew;
                }
            }
        } else if (tid < 384) {
            int d = tid - 256;
            s->ctlX[r][d] = x[b * TT * DD + t * DD + d];
        }
        __syncthreads();

        // ---- P3: read_input = rW @ M, single phase with warp butterfly reduce ----
        {
            int half = lane >> 4;            // 0/1
            int sub  = lane & 15;
            int task = warp * 2 + half;      // 0..31 = h*8 + d4
            int h = task >> 3, d4 = task & 7;
            const float4* M4 = reinterpret_cast<const float4*>(s->M);
            const float* rwh = &s->rW[h * NSLOT];
            float4 a = make_float4(0.f, 0.f, 0.f, 0.f);
#pragma unroll
            for (int i = 0; i < 8; ++i) {
                int n = sub + i * 16;        // stride-16 rows: conflict-free phases
                float4 mm = M4[n * 9 + d4];
                float w = rwh[n];
                a.x += w * mm.x; a.y += w * mm.y; a.z += w * mm.z; a.w += w * mm.w;
            }
#pragma unroll
            for (int off = 8; off > 0; off >>= 1) {
                a.x += __shfl_xor_sync(0xffffffffu, a.x, off);
                a.y += __shfl_xor_sync(0xffffffffu, a.y, off);
                a.z += __shfl_xor_sync(0xffffffffu, a.z, off);
                a.w += __shfl_xor_sync(0xffffffffu, a.w, off);
            }
            if (sub == 0)
                reinterpret_cast<float4*>(&s->ctlX[r][DD])[task] = a;
        }
        // ---- S1: ctl ready; gather peers' ctl ----
        cl.sync();
        if (tid < 192) {
            int p = tid / 64, q = tid & 63;
            int pr = p + (p >= r);
            const float4* src = (const float4*)cl.map_shared_rank((void*)s->ctlX[pr], pr);
            reinterpret_cast<float4*>(s->ctlX[pr])[q] = src[q];
        }
        __syncthreads();

        // ---- P4: hctl quarter for ALL 4 batches; weight amortized over batches ----
        if (tid < 256) {
            int col4 = tid & 15, seg = tid >> 4;      // 16 segs x 16 rows
            const float4* wp = reinterpret_cast<const float4*>(s->wpinC);
            float4 a[CLN];
#pragma unroll
            for (int bi = 0; bi < CLN; ++bi) a[bi] = make_float4(0.f, 0.f, 0.f, 0.f);
            int n0 = seg * 16;
#pragma unroll 4
            for (int n = n0; n < n0 + 16; ++n) {
                float4 w = wp[n * 16 + col4];
#pragma unroll
                for (int bi = 0; bi < CLN; ++bi) {
                    float v = s->ctlX[bi][n];
                    a[bi].x += v * w.x; a[bi].y += v * w.y;
                    a[bi].z += v * w.z; a[bi].w += v * w.w;
                }
            }
            int slot = (seg * 16 + col4) * 17;
#pragma unroll
            for (int bi = 0; bi < CLN; ++bi) {
                s->red[slot + bi * 4 + 0] = a[bi].x;
                s->red[slot + bi * 4 + 1] = a[bi].y;
                s->red[slot + bi * 4 + 2] = a[bi].z;
                s->red[slot + bi * 4 + 3] = a[bi].w;
            }
        }
        __syncthreads();
        if (tid < 256) {
            int bi = tid >> 6, c = tid & 63;
            int base = (c >> 2) * 17 + bi * 4 + (c & 3);
            float a = s->bc_s[c];
#pragma unroll
            for (int seg = 0; seg < 16; ++seg) a += s->red[seg * 16 * 17 + base];
            s->hctl_q[bi][c] = fmaxf(a, 0.f);     // local only: no exchange needed
        }
        __syncthreads();

        // ---- P5: o k-partial (full 384 cols), weight amortized, kseg shuffle ----
        // 12 warps; lane = kseg*8 + c8; col4 = warp*8 + c8; kseg covers 16 rows
        if (tid < 384) {
            int c8   = lane & 7;
            int kseg = lane >> 3;
            int col4 = warp * 8 + c8;
            const float4* wp = reinterpret_cast<const float4*>(s->wpinF);
            float4 a[CLN];
#pragma unroll
            for (int bi = 0; bi < CLN; ++bi) a[bi] = make_float4(0.f, 0.f, 0.f, 0.f);
            int n0 = kseg * 16;
#pragma unroll 4
            for (int n = n0; n < n0 + 16; ++n) {
                float4 w = wp[n * 96 + col4];
#pragma unroll
                for (int bi = 0; bi < CLN; ++bi) {
                    float v = s->hctl_q[bi][n];
                    a[bi].x += v * w.x; a[bi].y += v * w.y;
                    a[bi].z += v * w.z; a[bi].w += v * w.w;
                }
            }
#pragma unroll
            for (int off = 8; off <= 16; off <<= 1) {
#pragma unroll
                for (int bi = 0; bi < CLN; ++bi) {
                    a[bi].x += __shfl_xor_sync(0xffffffffu, a[bi].x, off);
                    a[bi].y += __shfl_xor_sync(0xffffffffu, a[bi].y, off);
                    a[bi].z += __shfl_xor_sync(0xffffffffu, a[bi].z, off);
                    a[bi].w += __shfl_xor_sync(0xffffffffu, a[bi].w, off);
                }
            }
            if (kseg == 0) {
#pragma unroll
                for (int bi = 0; bi < CLN; ++bi)
                    reinterpret_cast<float4*>(s->opart[bi])[col4] = a[bi];
            }
        }
        // ---- S2: o-partials ready; owner CTA reduces its batch's 4 partials ----
        cl.sync();
        if (tid < 96) {
            int q = tid;
            float4 acc = reinterpret_cast<const float4*>(s->opart[r])[q];
#pragma unroll
            for (int p = 0; p < 3; ++p) {
                int pr = p + (p >= r);
                const float4* src = (const float4*)cl.map_shared_rank((void*)s->opart[r], pr);
                float4 v = src[q];
                acc.x += v.x; acc.y += v.y; acc.z += v.z; acc.w += v.w;
            }
            float4 bv = reinterpret_cast<const float4*>(s->bf_s)[q];
            acc.x += bv.x; acc.y += bv.y; acc.z += bv.z; acc.w += bv.w;
            reinterpret_cast<float4*>(s->o_full)[q] = acc;
        }
        __syncthreads();

        // ---- BETA: write addressing (w0-3, in-reg kinvw) | out emit | rv stash ----
        if (warp < HH) {
            fused_address(s, &s->o_full[CTLW + warp * BITS], s->wW, warp, lane);
        } else if (tid < 256) {
            out[b * TT * DD + t * DD + (tid - 128)] = s->o_full[tid - 128];
        } else if (tid < 384) {
            s->rv[tid - 256] = s->o_full[tid - 128];
        }
        __syncthreads();

        // ---- P8: M update + fused M-norms (pre-Pt wW) ----
        {
            int n  = tid >> 2;
            int d8 = (tid & 3) * 8;
            float w0 = s->wW[n], w1 = s->wW[NSLOT + n];
            float w2 = s->wW[2 * NSLOT + n], w3 = s->wW[3 * NSLOT + n];
            float ss = 0.f;
            float4* Mp = reinterpret_cast<float4*>(&s->M[n * MPITCH + d8]);
#pragma unroll
            for (int q = 0; q < 2; ++q) {
                int db = d8 + q * 4;
                float4 mv = Mp[q];
                float4 e0 = *reinterpret_cast<const float4*>(&s->er_s[0 * BITS + db]);
                float4 e1 = *reinterpret_cast<const float4*>(&s->er_s[1 * BITS + db]);
                float4 e2 = *reinterpret_cast<const float4*>(&s->er_s[2 * BITS + db]);
                float4 e3 = *reinterpret_cast<const float4*>(&s->er_s[3 * BITS + db]);
                float4 a0 = *reinterpret_cast<const float4*>(&s->ad_s[0 * BITS + db]);
                float4 a1 = *reinterpret_cast<const float4*>(&s->ad_s[1 * BITS + db]);
                float4 a2 = *reinterpret_cast<const float4*>(&s->ad_s[2 * BITS + db]);
                float4 a3 = *reinterpret_cast<const float4*>(&s->ad_s[3 * BITS + db]);
                float4 nm;
                float ew, aw;
                ew = w0*e0.x + w1*e1.x + w2*e2.x + w3*e3.x;
                aw = w0*a0.x + w1*a1.x + w2*a2.x + w3*a3.x;
                nm.x = mv.x * (1.f - ew) + aw;
                ew = w0*e0.y + w1*e1.y + w2*e2.y + w3*e3.y;
                aw = w0*a0.y + w1*a1.y + w2*a2.y + w3*a3.y;
                nm.y = mv.y * (1.f - ew) + aw;
                ew = w0*e0.z + w1*e1.z + w2*e2.z + w3*e3.z;
                aw = w0*a0.z + w1*a1.z + w2*a2.z + w3*a3.z;
                nm.z = mv.z * (1.f - ew) + aw;
                ew = w0*e0.w + w1*e1.w + w2*e2.w + w3*e3.w;
                aw = w0*a0.w + w1*a1.w + w2*a2.w + w3*a3.w;
                nm.w = mv.w * (1.f - ew) + aw;
                Mp[q] = nm;
                ss += nm.x*nm.x + nm.y*nm.y + nm.z*nm.z + nm.w*nm.w;
            }
            ss += __shfl_xor_sync(0xffffffffu, ss, 1);
            ss += __shfl_xor_sync(0xffffffffu, ss, 2);
            if ((tid & 3) == 0) s->minv[n] = rsqrtf(fmaxf(ss, 1e-12f));
        }
        __syncthreads();
    }
    cl.sync();   // no CTA exits while peers' DSMEM pulls could be in flight
}

extern "C" void kernel_launch(void* const* d_in, const int* in_sizes, int n_in,
                              void* d_out, int out_size)
{
    const float* x       = (const float*)d_in[0];
    const float* beta    = (const float*)d_in[1];
    const float* g       = (const float*)d_in[2];
    const float* erase   = (const float*)d_in[3];
    const float* add     = (const float*)d_in[4];
    const float* Wg      = (const float*)d_in[5];
    const float* M0      = (const float*)d_in[6];
    const float* read0   = (const float*)d_in[7];
    const float* readW0  = (const float*)d_in[8];
    const float* writeW0 = (const float*)d_in[9];
    // d_in[10] = S0   (dead)
    const float* Wc      = (const float*)d_in[11];
    const float* bc      = (const float*)d_in[12];
    const float* Wf      = (const float*)d_in[13];
    const float* bf      = (const float*)d_in[14];
    // d_in[15..17] = Wi, Ui, b_gru (dead)

    (void)in_sizes; (void)n_in; (void)out_size;

    cudaFuncSetAttribute(uic_kernel, cudaFuncAttributeMaxDynamicSharedMemorySize,
                         (int)sizeof(SmemLayout));
    uic_kernel<<<BB, THREADS, sizeof(SmemLayout)>>>(x, beta, g, erase, add, Wg,
                                                    M0, read0, readW0, writeW0,
                                                    Wc, bc, Wf, bf, (float*)d_out);
}